// round 8
// baseline (speedup 1.0000x reference)
#include <cuda_runtime.h>
#include <cuda_fp16.h>
#include <math.h>
#include <cstdint>

#define N_NODES 100000
#define N_EDGES 50000
#define D 128
#define MAX_NNZ 1600000
#define T_CNT (N_EDGES + N_NODES)
#define SCAN_CHUNK 1024
#define SCAN_NB ((T_CNT + SCAN_CHUNK - 1) / SCAN_CHUNK)   // 147 blocks (all co-resident)

// ---------------------------------------------------------------------------
// Device-global scratch (fp16 Xp/Xe only)
// ---------------------------------------------------------------------------
__device__ unsigned int g_Xph[(size_t)N_NODES * (D/2)];  // fp16 Xp
__device__ unsigned int g_Xeh[(size_t)N_EDGES * (D/2)];  // fp16 Xe
__device__ int g_cnt[T_CNT];
__device__ int g_off[T_CNT + 1];
__device__ int g_cur[T_CNT];
__device__ int g_list[2 * MAX_NNZ];
__device__ int g_tick;
__device__ int g_flagv[SCAN_NB];
__device__ int g_partialv[SCAN_NB];

// ---------------------------------------------------------------------------
// K: zero counters + lookback state
// ---------------------------------------------------------------------------
__global__ void zero_cnt_kernel() {
    int i = blockIdx.x * blockDim.x + threadIdx.x;
    if (i < T_CNT) g_cnt[i] = 0;
    if (i < SCAN_NB) { g_flagv[i] = 0; g_partialv[i] = 0; }
    if (i == 0) g_tick = 0;
}

__global__ __launch_bounds__(256) void hist_kernel(
    const int* __restrict__ vertex, const int* __restrict__ edges, int nnz)
{
    int i = blockIdx.x * blockDim.x + threadIdx.x;
    if (i >= nnz) return;
    atomicAdd(&g_cnt[edges[i]], 1);
    atomicAdd(&g_cnt[N_EDGES + vertex[i]], 1);
}

// ---------------------------------------------------------------------------
// K: single-pass exclusive scan (decoupled lookback, ticket-chained)
// ---------------------------------------------------------------------------
__global__ __launch_bounds__(1024) void scan_lookback_kernel() {
    __shared__ int s_b;
    __shared__ int s_prev;
    __shared__ int wsum[32];

    if (threadIdx.x == 0) s_b = atomicAdd(&g_tick, 1);
    __syncthreads();
    int b = s_b;

    int i = b * SCAN_CHUNK + threadIdx.x;
    int v = (i < T_CNT) ? g_cnt[i] : 0;
    int lane = threadIdx.x & 31, wid = threadIdx.x >> 5;
    int x = v;
#pragma unroll
    for (int o = 1; o < 32; o <<= 1) {
        int y = __shfl_up_sync(0xffffffffu, x, o);
        if (lane >= o) x += y;
    }
    if (lane == 31) wsum[wid] = x;
    __syncthreads();
    if (wid == 0) {
        int w = wsum[lane];
#pragma unroll
        for (int o = 1; o < 32; o <<= 1) {
            int y = __shfl_up_sync(0xffffffffu, w, o);
            if (lane >= o) w += y;
        }
        wsum[lane] = w;
    }
    __syncthreads();
    int base = (wid > 0) ? wsum[wid - 1] : 0;
    int incl = x + base;                      // block-local inclusive

    if (threadIdx.x == SCAN_CHUNK - 1) {
        int prev = 0;
        if (b > 0) {
            while (atomicAdd(&g_flagv[b - 1], 0) == 0) { __nanosleep(64); }
            prev = atomicAdd(&g_partialv[b - 1], 0);
        }
        g_partialv[b] = prev + incl;          // incl @ last thread == block total
        __threadfence();
        atomicExch(&g_flagv[b], 1);
        s_prev = prev;
        if (b == SCAN_NB - 1) g_off[T_CNT] = prev + incl;
    }
    __syncthreads();
    int prev = s_prev;

    if (i < T_CNT) {
        int o = prev + incl - v;
        g_off[i] = o;
        g_cur[i] = o;
    }
}

__global__ __launch_bounds__(256) void fill_kernel(
    const int* __restrict__ vertex, const int* __restrict__ edges, int nnz)
{
    int i = blockIdx.x * blockDim.x + threadIdx.x;
    if (i >= nnz) return;
    int e = edges[i], v = vertex[i];
    int p = atomicAdd(&g_cur[e], 1);
    g_list[p] = v;
    int q = atomicAdd(&g_cur[N_EDGES + v], 1);
    g_list[q] = e;
}

// ---------------------------------------------------------------------------
// TF32 mma.sync GEMM: Xph = fp16(X @ W)   (persistent, W resident in SMEM)
// ---------------------------------------------------------------------------
#define AP 132
#define BP 136
#define GEMM_SMEM ((128 * AP + 128 * BP) * 4)

__device__ __forceinline__ float cvt_tf32(float x) {
    float r;
    asm("cvt.rn.tf32.f32 %0, %1;" : "=f"(r) : "f"(x));
    return r;
}

__global__ __launch_bounds__(256) void gemm_kernel(
    const float* __restrict__ X, const float* __restrict__ W, int M)
{
    extern __shared__ float smem[];
    float* As = smem;
    float* Bs = smem + 128 * AP;

    int tid  = threadIdx.x;
    int wid  = tid >> 5;
    int lane = tid & 31;
    int gid  = lane >> 2;
    int tig  = lane & 3;

    for (int i = tid; i < 128 * 32; i += 256) {
        int k  = i >> 5;
        int c4 = (i & 31) << 2;
        float4 v = *(const float4*)(W + (size_t)k * D + c4);
        v.x = cvt_tf32(v.x); v.y = cvt_tf32(v.y);
        v.z = cvt_tf32(v.z); v.w = cvt_tf32(v.w);
        *(float4*)&Bs[k * BP + c4] = v;
    }

    int n_tiles = (M + 127) >> 7;
    int mrow = wid * 16;

    for (int tile = blockIdx.x; tile < n_tiles; tile += gridDim.x) {
        int row0 = tile << 7;

        for (int i = tid; i < 128 * 32; i += 256) {
            int m  = i >> 5;
            int c4 = (i & 31) << 2;
            int gm = row0 + m;
            if (gm >= M) gm = M - 1;
            float4 v = *(const float4*)(X + (size_t)gm * D + c4);
            v.x = cvt_tf32(v.x); v.y = cvt_tf32(v.y);
            v.z = cvt_tf32(v.z); v.w = cvt_tf32(v.w);
            *(float4*)&As[m * AP + c4] = v;
        }
        __syncthreads();

        float acc[16][4];
#pragma unroll
        for (int nt = 0; nt < 16; nt++)
#pragma unroll
            for (int q = 0; q < 4; q++) acc[nt][q] = 0.f;

#pragma unroll
        for (int ks = 0; ks < 16; ks++) {
            int k = ks << 3;
            uint32_t a0 = __float_as_uint(As[(mrow + gid)     * AP + k + tig]);
            uint32_t a1 = __float_as_uint(As[(mrow + gid + 8) * AP + k + tig]);
            uint32_t a2 = __float_as_uint(As[(mrow + gid)     * AP + k + tig + 4]);
            uint32_t a3 = __float_as_uint(As[(mrow + gid + 8) * AP + k + tig + 4]);
#pragma unroll
            for (int nt = 0; nt < 16; nt++) {
                uint32_t b0 = __float_as_uint(Bs[(k + tig)     * BP + nt * 8 + gid]);
                uint32_t b1 = __float_as_uint(Bs[(k + tig + 4) * BP + nt * 8 + gid]);
                asm volatile(
                    "mma.sync.aligned.m16n8k8.row.col.f32.tf32.tf32.f32 "
                    "{%0,%1,%2,%3}, {%4,%5,%6,%7}, {%8,%9}, {%0,%1,%2,%3};"
                    : "+f"(acc[nt][0]), "+f"(acc[nt][1]), "+f"(acc[nt][2]), "+f"(acc[nt][3])
                    : "r"(a0), "r"(a1), "r"(a2), "r"(a3), "r"(b0), "r"(b1));
            }
        }
        __syncthreads();

        int gm0 = row0 + mrow + gid;
        int gm1 = gm0 + 8;
        bool v0 = gm0 < M, v1 = gm1 < M;
#pragma unroll
        for (int nt = 0; nt < 16; nt++) {
            int col = nt * 8 + tig * 2;
            if (v0) {
                __half2 h = __float22half2_rn(make_float2(acc[nt][0], acc[nt][1]));
                g_Xph[(size_t)gm0 * (D/2) + (col >> 1)] = *(unsigned int*)&h;
            }
            if (v1) {
                __half2 h = __float22half2_rn(make_float2(acc[nt][2], acc[nt][3]));
                g_Xph[(size_t)gm1 * (D/2) + (col >> 1)] = *(unsigned int*)&h;
            }
        }
    }
}

// ---------------------------------------------------------------------------
// Pair-row warp segment sum: 16 lanes x uint4 per row => 2 rows per warp-LDG.
// shfl_xor(16) folds the halves; every lane ends with sums for its 8 columns.
// ---------------------------------------------------------------------------
__device__ __forceinline__ void seg_sum_pair(
    const uint4* __restrict__ src,      // fp16 rows, 16 uint4 per row
    int start, int end, int lane, float acc[8])
{
    int half = lane >> 4;               // 0: even rows, 1: odd rows
    int sub  = lane & 15;
    for (int j = start; j < end; j += 32) {
        int cnt = end - j;
        if (cnt > 32) cnt = 32;
        int idx = (lane < cnt) ? __ldg(g_list + j + lane) : -1;
#pragma unroll 4
        for (int t = 0; t < cnt; t += 2) {
            int r0 = __shfl_sync(0xffffffffu, idx, t);
            int r1 = __shfl_sync(0xffffffffu, idx, t + 1);  // -1 if t+1>=cnt
            int row = half ? r1 : r0;
            if (row >= 0) {
                uint4 hv = __ldg(src + (size_t)row * 16 + sub);
                float2 f;
                f = __half22float2(*(const __half2*)&hv.x); acc[0] += f.x; acc[1] += f.y;
                f = __half22float2(*(const __half2*)&hv.y); acc[2] += f.x; acc[3] += f.y;
                f = __half22float2(*(const __half2*)&hv.z); acc[4] += f.x; acc[5] += f.y;
                f = __half22float2(*(const __half2*)&hv.w); acc[6] += f.x; acc[7] += f.y;
            }
        }
    }
#pragma unroll
    for (int q = 0; q < 8; q++)
        acc[q] += __shfl_xor_sync(0xffffffffu, acc[q], 16);
}

// ---------------------------------------------------------------------------
// Pass 1: Xe[e] = sum of incident Xp rows
// ---------------------------------------------------------------------------
__global__ __launch_bounds__(256) void gather_edge_kernel() {
    int warp = (blockIdx.x * blockDim.x + threadIdx.x) >> 5;
    if (warp >= N_EDGES) return;
    int lane = threadIdx.x & 31;
    int sub  = lane & 15;
    int half = lane >> 4;
    float acc[8] = {0.f,0.f,0.f,0.f,0.f,0.f,0.f,0.f};
    seg_sum_pair((const uint4*)g_Xph, g_off[warp], g_off[warp + 1], lane, acc);
    __half2 h0 = __float22half2_rn(make_float2(acc[half*4+0], acc[half*4+1]));
    __half2 h1 = __float22half2_rn(make_float2(acc[half*4+2], acc[half*4+3]));
    uint2 o = make_uint2(*(unsigned int*)&h0, *(unsigned int*)&h1);
    ((uint2*)g_Xeh)[(size_t)warp * 32 + sub * 2 + half] = o;
}

// ---------------------------------------------------------------------------
// Pass 2: out[v] = gelu((1+eps)*Xp[v] + sum of incident Xe rows)
// ---------------------------------------------------------------------------
__device__ __forceinline__ float gelu_exact(float x) {
    return 0.5f * x * (1.0f + erff(x * 0.70710678118654752440f));
}

__global__ __launch_bounds__(256) void gather_node_kernel(
    float* __restrict__ out, const float* __restrict__ eps, int M)
{
    int warp = (blockIdx.x * blockDim.x + threadIdx.x) >> 5;
    if (warp >= M) return;
    int lane = threadIdx.x & 31;
    int sub  = lane & 15;
    int half = lane >> 4;
    float acc[8] = {0.f,0.f,0.f,0.f,0.f,0.f,0.f,0.f};
    seg_sum_pair((const uint4*)g_Xeh, g_off[N_EDGES + warp], g_off[N_EDGES + warp + 1],
                 lane, acc);

    float s = 1.0f + __ldg(eps);
    uint2 ph = __ldg((const uint2*)g_Xph + (size_t)warp * 32 + sub * 2 + half);
    float2 p0 = __half22float2(*(const __half2*)&ph.x);
    float2 p1 = __half22float2(*(const __half2*)&ph.y);
    float4 r;
    r.x = gelu_exact(fmaf(s, p0.x, acc[half*4+0]));
    r.y = gelu_exact(fmaf(s, p0.y, acc[half*4+1]));
    r.z = gelu_exact(fmaf(s, p1.x, acc[half*4+2]));
    r.w = gelu_exact(fmaf(s, p1.y, acc[half*4+3]));
    ((float4*)out)[(size_t)warp * 32 + sub * 2 + half] = r;
}

// ---------------------------------------------------------------------------
// Launch: GEMM forked onto a second stream, CSR chain on the capture stream.
// ---------------------------------------------------------------------------
extern "C" void kernel_launch(void* const* d_in, const int* in_sizes, int n_in,
                              void* d_out, int out_size)
{
    const float* X      = (const float*)d_in[0];
    const float* W      = (const float*)d_in[1];
    const float* eps    = (const float*)d_in[2];
    const int*   vertex = (const int*)d_in[3];
    const int*   edges  = (const int*)d_in[4];
    float*       out    = (float*)d_out;

    int nnz = in_sizes[3];
    int M   = in_sizes[0] / D;

    static cudaStream_t s_gemm = nullptr;
    static cudaEvent_t  e_fork = nullptr, e_gemm = nullptr;
    if (!s_gemm) {
        cudaStreamCreateWithFlags(&s_gemm, cudaStreamNonBlocking);
        cudaEventCreateWithFlags(&e_fork, cudaEventDisableTiming);
        cudaEventCreateWithFlags(&e_gemm, cudaEventDisableTiming);
        cudaFuncSetAttribute(gemm_kernel,
                             cudaFuncAttributeMaxDynamicSharedMemorySize, GEMM_SMEM);
    }

    cudaEventRecord(e_fork, 0);
    cudaStreamWaitEvent(s_gemm, e_fork, 0);
    gemm_kernel<<<148, 256, GEMM_SMEM, s_gemm>>>(X, W, M);
    cudaEventRecord(e_gemm, s_gemm);

    zero_cnt_kernel<<<(T_CNT + 255) / 256, 256>>>();
    hist_kernel<<<(nnz + 255) / 256, 256>>>(vertex, edges, nnz);
    scan_lookback_kernel<<<SCAN_NB, SCAN_CHUNK>>>();
    fill_kernel<<<(nnz + 255) / 256, 256>>>(vertex, edges, nnz);

    cudaStreamWaitEvent(0, e_gemm, 0);
    gather_edge_kernel<<<(N_EDGES * 32 + 255) / 256, 256>>>();
    gather_node_kernel<<<(M * 32 + 255) / 256, 256>>>(out, eps, M);
}

// round 10
// speedup vs baseline: 2.2854x; 2.2854x over previous
#include <cuda_runtime.h>
#include <cuda_fp16.h>
#include <math.h>
#include <cstdint>

#define N_NODES 100000
#define N_EDGES 50000
#define D 128
#define MAX_NNZ 1600000
#define T_CNT (N_EDGES + N_NODES)
#define SCAN_CHUNK 1024
#define SCAN_NB ((T_CNT + SCAN_CHUNK - 1) / SCAN_CHUNK)

// ---------------------------------------------------------------------------
// Device-global scratch (fp16 Xp/Xe only)
// ---------------------------------------------------------------------------
__device__ unsigned int g_Xph[(size_t)N_NODES * (D/2)];  // fp16 Xp
__device__ unsigned int g_Xeh[(size_t)N_EDGES * (D/2)];  // fp16 Xe
__device__ int g_cnt[T_CNT];
__device__ int g_off[T_CNT + 1];
__device__ int g_cur[T_CNT];
__device__ int g_bsum[SCAN_NB];
__device__ int g_list[2 * MAX_NNZ];

// ---------------------------------------------------------------------------
// CSR build (3-kernel scan — proven fast)
// ---------------------------------------------------------------------------
__global__ void zero_cnt_kernel() {
    int i = blockIdx.x * blockDim.x + threadIdx.x;
    if (i < T_CNT) g_cnt[i] = 0;
}

__global__ __launch_bounds__(256) void hist_kernel(
    const int* __restrict__ vertex, const int* __restrict__ edges, int nnz)
{
    int i = blockIdx.x * blockDim.x + threadIdx.x;
    if (i >= nnz) return;
    atomicAdd(&g_cnt[edges[i]], 1);
    atomicAdd(&g_cnt[N_EDGES + vertex[i]], 1);
}

__global__ __launch_bounds__(1024) void scan1_kernel() {
    int b = blockIdx.x;
    int i = b * SCAN_CHUNK + threadIdx.x;
    int v = (i < T_CNT) ? g_cnt[i] : 0;
    int lane = threadIdx.x & 31, wid = threadIdx.x >> 5;
    int x = v;
#pragma unroll
    for (int o = 1; o < 32; o <<= 1) {
        int y = __shfl_up_sync(0xffffffffu, x, o);
        if (lane >= o) x += y;
    }
    __shared__ int wsum[32];
    if (lane == 31) wsum[wid] = x;
    __syncthreads();
    if (wid == 0) {
        int w = wsum[lane];
#pragma unroll
        for (int o = 1; o < 32; o <<= 1) {
            int y = __shfl_up_sync(0xffffffffu, w, o);
            if (lane >= o) w += y;
        }
        wsum[lane] = w;
    }
    __syncthreads();
    int base = (wid > 0) ? wsum[wid - 1] : 0;
    int incl = x + base;
    if (i < T_CNT) g_off[i] = incl - v;
    if (threadIdx.x == SCAN_CHUNK - 1) g_bsum[b] = incl;
}

__global__ __launch_bounds__(256) void scan2_kernel() {
    __shared__ int s[256];
    int t = threadIdx.x;
    int v = (t < SCAN_NB) ? g_bsum[t] : 0;
    s[t] = v;
    __syncthreads();
    for (int o = 1; o < 256; o <<= 1) {
        int y = (t >= o) ? s[t - o] : 0;
        __syncthreads();
        s[t] += y;
        __syncthreads();
    }
    if (t < SCAN_NB) g_bsum[t] = s[t] - v;
}

__global__ __launch_bounds__(1024) void scan3_kernel(int total) {
    int i = blockIdx.x * SCAN_CHUNK + threadIdx.x;
    if (i < T_CNT) {
        int o = g_off[i] + g_bsum[blockIdx.x];
        g_off[i] = o;
        g_cur[i] = o;
    }
    if (i == 0) g_off[T_CNT] = total;
}

__global__ __launch_bounds__(256) void fill_kernel(
    const int* __restrict__ vertex, const int* __restrict__ edges, int nnz)
{
    int i = blockIdx.x * blockDim.x + threadIdx.x;
    if (i >= nnz) return;
    int e = edges[i], v = vertex[i];
    int p = atomicAdd(&g_cur[e], 1);
    g_list[p] = v;
    int q = atomicAdd(&g_cur[N_EDGES + v], 1);
    g_list[q] = e;
}

// ---------------------------------------------------------------------------
// TF32 mma.sync GEMM: Xph = fp16(X @ W)   (persistent, W resident in SMEM)
// ---------------------------------------------------------------------------
#define AP 132
#define BP 136
#define GEMM_SMEM ((128 * AP + 128 * BP) * 4)

__device__ __forceinline__ float cvt_tf32(float x) {
    float r;
    asm("cvt.rn.tf32.f32 %0, %1;" : "=f"(r) : "f"(x));
    return r;
}

__global__ __launch_bounds__(256) void gemm_kernel(
    const float* __restrict__ X, const float* __restrict__ W, int M)
{
    extern __shared__ float smem[];
    float* As = smem;
    float* Bs = smem + 128 * AP;

    int tid  = threadIdx.x;
    int wid  = tid >> 5;
    int lane = tid & 31;
    int gid  = lane >> 2;
    int tig  = lane & 3;

    for (int i = tid; i < 128 * 32; i += 256) {
        int k  = i >> 5;
        int c4 = (i & 31) << 2;
        float4 v = *(const float4*)(W + (size_t)k * D + c4);
        v.x = cvt_tf32(v.x); v.y = cvt_tf32(v.y);
        v.z = cvt_tf32(v.z); v.w = cvt_tf32(v.w);
        *(float4*)&Bs[k * BP + c4] = v;
    }

    int n_tiles = (M + 127) >> 7;
    int mrow = wid * 16;

    for (int tile = blockIdx.x; tile < n_tiles; tile += gridDim.x) {
        int row0 = tile << 7;

        for (int i = tid; i < 128 * 32; i += 256) {
            int m  = i >> 5;
            int c4 = (i & 31) << 2;
            int gm = row0 + m;
            if (gm >= M) gm = M - 1;
            float4 v = *(const float4*)(X + (size_t)gm * D + c4);
            v.x = cvt_tf32(v.x); v.y = cvt_tf32(v.y);
            v.z = cvt_tf32(v.z); v.w = cvt_tf32(v.w);
            *(float4*)&As[m * AP + c4] = v;
        }
        __syncthreads();

        float acc[16][4];
#pragma unroll
        for (int nt = 0; nt < 16; nt++)
#pragma unroll
            for (int q = 0; q < 4; q++) acc[nt][q] = 0.f;

#pragma unroll
        for (int ks = 0; ks < 16; ks++) {
            int k = ks << 3;
            uint32_t a0 = __float_as_uint(As[(mrow + gid)     * AP + k + tig]);
            uint32_t a1 = __float_as_uint(As[(mrow + gid + 8) * AP + k + tig]);
            uint32_t a2 = __float_as_uint(As[(mrow + gid)     * AP + k + tig + 4]);
            uint32_t a3 = __float_as_uint(As[(mrow + gid + 8) * AP + k + tig + 4]);
#pragma unroll
            for (int nt = 0; nt < 16; nt++) {
                uint32_t b0 = __float_as_uint(Bs[(k + tig)     * BP + nt * 8 + gid]);
                uint32_t b1 = __float_as_uint(Bs[(k + tig + 4) * BP + nt * 8 + gid]);
                asm volatile(
                    "mma.sync.aligned.m16n8k8.row.col.f32.tf32.tf32.f32 "
                    "{%0,%1,%2,%3}, {%4,%5,%6,%7}, {%8,%9}, {%0,%1,%2,%3};"
                    : "+f"(acc[nt][0]), "+f"(acc[nt][1]), "+f"(acc[nt][2]), "+f"(acc[nt][3])
                    : "r"(a0), "r"(a1), "r"(a2), "r"(a3), "r"(b0), "r"(b1));
            }
        }
        __syncthreads();

        int gm0 = row0 + mrow + gid;
        int gm1 = gm0 + 8;
        bool v0 = gm0 < M, v1 = gm1 < M;
#pragma unroll
        for (int nt = 0; nt < 16; nt++) {
            int col = nt * 8 + tig * 2;
            if (v0) {
                __half2 h = __float22half2_rn(make_float2(acc[nt][0], acc[nt][1]));
                g_Xph[(size_t)gm0 * (D/2) + (col >> 1)] = *(unsigned int*)&h;
            }
            if (v1) {
                __half2 h = __float22half2_rn(make_float2(acc[nt][2], acc[nt][3]));
                g_Xph[(size_t)gm1 * (D/2) + (col >> 1)] = *(unsigned int*)&h;
            }
        }
    }
}

// ---------------------------------------------------------------------------
// Warp segment sum over fp16 rows (uint2/lane, 8-deep unroll — proven form)
// ---------------------------------------------------------------------------
__device__ __forceinline__ void acc_row_h(
    const uint2* __restrict__ src, int r, int lane, float4& acc)
{
    uint2 hv = __ldg(src + (size_t)r * 32 + lane);
    float2 f0 = __half22float2(*(const __half2*)&hv.x);
    float2 f1 = __half22float2(*(const __half2*)&hv.y);
    acc.x += f0.x; acc.y += f0.y; acc.z += f1.x; acc.w += f1.y;
}

__device__ __forceinline__ void warp_segment_sum_h(
    const uint2* __restrict__ src, int start, int end, int lane, float4& acc)
{
    for (int j = start; j < end; j += 32) {
        int n = end - j;
        int cnt = n < 32 ? n : 32;
        int idx = (lane < cnt) ? __ldg(g_list + j + lane) : 0;
        int t = 0;
        for (; t + 8 <= cnt; t += 8) {
#pragma unroll
            for (int u = 0; u < 8; u++) {
                int r = __shfl_sync(0xffffffffu, idx, t + u);
                acc_row_h(src, r, lane, acc);
            }
        }
        for (; t < cnt; t++) {
            int r = __shfl_sync(0xffffffffu, idx, t);
            acc_row_h(src, r, lane, acc);
        }
    }
}

__global__ __launch_bounds__(256) void gather_edge_kernel() {
    int warp = (blockIdx.x * blockDim.x + threadIdx.x) >> 5;
    if (warp >= N_EDGES) return;
    int lane = threadIdx.x & 31;
    float4 acc = make_float4(0.f, 0.f, 0.f, 0.f);
    warp_segment_sum_h((const uint2*)g_Xph, g_off[warp], g_off[warp + 1], lane, acc);
    __half2 h0 = __float22half2_rn(make_float2(acc.x, acc.y));
    __half2 h1 = __float22half2_rn(make_float2(acc.z, acc.w));
    uint2 o = make_uint2(*(unsigned int*)&h0, *(unsigned int*)&h1);
    ((uint2*)g_Xeh)[(size_t)warp * 32 + lane] = o;
}

__device__ __forceinline__ float gelu_exact(float x) {
    return 0.5f * x * (1.0f + erff(x * 0.70710678118654752440f));
}

__global__ __launch_bounds__(256) void gather_node_kernel(
    float* __restrict__ out, const float* __restrict__ eps, int M)
{
    int warp = (blockIdx.x * blockDim.x + threadIdx.x) >> 5;
    if (warp >= M) return;
    int lane = threadIdx.x & 31;
    float4 acc = make_float4(0.f, 0.f, 0.f, 0.f);
    warp_segment_sum_h((const uint2*)g_Xeh, g_off[N_EDGES + warp], g_off[N_EDGES + warp + 1],
                 lane, acc);

    float s = 1.0f + __ldg(eps);
    uint2 ph = __ldg((const uint2*)g_Xph + (size_t)warp * 32 + lane);
    float2 p0 = __half22float2(*(const __half2*)&ph.x);
    float2 p1 = __half22float2(*(const __half2*)&ph.y);
    float4 r;
    r.x = gelu_exact(fmaf(s, p0.x, acc.x));
    r.y = gelu_exact(fmaf(s, p0.y, acc.y));
    r.z = gelu_exact(fmaf(s, p1.x, acc.z));
    r.w = gelu_exact(fmaf(s, p1.y, acc.w));
    ((float4*)out)[(size_t)warp * 32 + lane] = r;
}

// ---------------------------------------------------------------------------
// Launch: GEMM forked onto a second stream, CSR chain on the capture stream.
// ---------------------------------------------------------------------------
extern "C" void kernel_launch(void* const* d_in, const int* in_sizes, int n_in,
                              void* d_out, int out_size)
{
    const float* X      = (const float*)d_in[0];
    const float* W      = (const float*)d_in[1];
    const float* eps    = (const float*)d_in[2];
    const int*   vertex = (const int*)d_in[3];
    const int*   edges  = (const int*)d_in[4];
    float*       out    = (float*)d_out;

    int nnz = in_sizes[3];
    int M   = in_sizes[0] / D;

    static cudaStream_t s_gemm = nullptr;
    static cudaEvent_t  e_fork = nullptr, e_gemm = nullptr;
    if (!s_gemm) {
        cudaStreamCreateWithFlags(&s_gemm, cudaStreamNonBlocking);
        cudaEventCreateWithFlags(&e_fork, cudaEventDisableTiming);
        cudaEventCreateWithFlags(&e_gemm, cudaEventDisableTiming);
        cudaFuncSetAttribute(gemm_kernel,
                             cudaFuncAttributeMaxDynamicSharedMemorySize, GEMM_SMEM);
    }

    cudaEventRecord(e_fork, 0);
    cudaStreamWaitEvent(s_gemm, e_fork, 0);
    gemm_kernel<<<148, 256, GEMM_SMEM, s_gemm>>>(X, W, M);
    cudaEventRecord(e_gemm, s_gemm);

    zero_cnt_kernel<<<(T_CNT + 255) / 256, 256>>>();
    hist_kernel<<<(nnz + 255) / 256, 256>>>(vertex, edges, nnz);
    scan1_kernel<<<SCAN_NB, SCAN_CHUNK>>>();
    scan2_kernel<<<1, 256>>>();
    scan3_kernel<<<SCAN_NB, SCAN_CHUNK>>>(2 * nnz);
    fill_kernel<<<(nnz + 255) / 256, 256>>>(vertex, edges, nnz);

    cudaStreamWaitEvent(0, e_gemm, 0);
    gather_edge_kernel<<<(N_EDGES * 32 + 255) / 256, 256>>>();
    gather_node_kernel<<<(M * 32 + 255) / 256, 256>>>(out, eps, M);
}